// round 1
// baseline (speedup 1.0000x reference)
#include <cuda_runtime.h>
#include <cstdint>
#include <math.h>

// Problem constants
#define L_SEQ 2048
#define B_BATCH 64
#define ENC 512
#define ATTN 64
#define HIDDEN 512
#define M_TOTAL (L_SEQ * B_BATCH)   // 131072
#define NSPLIT 16

// Scratch (device globals; no allocation allowed)
__device__ float g_hidb[B_BATCH * ATTN];               // hid + b_attn, (b, a)
__device__ float g_scoresT[B_BATCH * L_SEQ];           // scores transposed (b, l)
__device__ float g_stats[B_BATCH * 2];                 // per-b: max, 1/sumexp
__device__ float g_partial[NSPLIT * B_BATCH * ENC];    // partial weighted sums

// ---------------- packed f32x2 helpers ----------------
__device__ __forceinline__ unsigned long long fma2(unsigned long long a,
                                                   unsigned long long b,
                                                   unsigned long long c) {
    asm("fma.rn.f32x2 %0, %1, %2, %3;" : "=l"(c) : "l"(a), "l"(b), "l"(c));
    return c;
}
__device__ __forceinline__ unsigned long long dup2(float x) {
    unsigned long long r;
    unsigned xu = __float_as_uint(x);
    asm("mov.b64 %0, {%1, %1};" : "=l"(r) : "r"(xu));
    return r;
}
__device__ __forceinline__ void unpack2(unsigned long long p, float& x, float& y) {
    unsigned lo, hi;
    asm("mov.b64 {%0, %1}, %2;" : "=r"(lo), "=r"(hi) : "l"(p));
    x = __uint_as_float(lo);
    y = __uint_as_float(hi);
}

// ---------------- Kernel 1: hid = hidden @ W_hidden + b_attn ----------------
__global__ void __launch_bounds__(64) hid_kernel(const float* __restrict__ hidden,
                                                 const float* __restrict__ Wh,
                                                 const float* __restrict__ b_attn) {
    __shared__ float sh[HIDDEN];
    int b = blockIdx.x;
    int tid = threadIdx.x;  // 0..63, column a
    for (int k = tid; k < HIDDEN; k += 64) sh[k] = hidden[b * HIDDEN + k];
    __syncthreads();
    float acc = b_attn[tid];
#pragma unroll 8
    for (int k = 0; k < HIDDEN; k++)
        acc = fmaf(sh[k], Wh[k * ATTN + tid], acc);
    g_hidb[b * ATTN + tid] = acc;
}

// ---------------- Kernel 2: projection GEMM + tanh*v -> scoresT -------------
// Block tile: 128 rows (m = l*64+b) x 64 cols, K chunks of 32.
// 256 threads: warp = col-group tc (8 cols), lane tr = row-group (4 rows).
__global__ void __launch_bounds__(256) score_kernel(const float* __restrict__ A,      // enc (M, 512)
                                                    const float* __restrict__ W,      // W_enc (512, 64)
                                                    const float* __restrict__ v) {
    __shared__ float As[32][132];   // [k][row], padded stride
    __shared__ float Bs[32][64];    // [k][col]
    __shared__ float red[8][128];

    const int tid = threadIdx.x;
    const int m0 = blockIdx.x * 128;
    const int tr = tid & 31;
    const int tc = tid >> 5;

    unsigned long long acc[4][4];
#pragma unroll
    for (int i = 0; i < 4; i++)
#pragma unroll
        for (int j = 0; j < 4; j++) acc[i][j] = 0ULL;

    const int arow = tid >> 3;   // 0..31
    const int akv  = tid & 7;    // 0..7  (float4 index along k)
    const int bk   = tid >> 4;   // 0..15
    const int bc   = tid & 15;   // 0..15 (float4 index along col)

    for (int kc = 0; kc < ENC; kc += 32) {
        // Load A tile 128x32 (float4 along k, scatter-transpose into As[k][row])
#pragma unroll
        for (int i = 0; i < 4; i++) {
            int r = arow + 32 * i;
            const float4 av = *(const float4*)(A + (size_t)(m0 + r) * ENC + kc + akv * 4);
            As[akv * 4 + 0][r] = av.x;
            As[akv * 4 + 1][r] = av.y;
            As[akv * 4 + 2][r] = av.z;
            As[akv * 4 + 3][r] = av.w;
        }
        // Load B tile 32x64
#pragma unroll
        for (int i = 0; i < 2; i++) {
            int kr = bk + 16 * i;
            const float4 bv = *(const float4*)(W + (size_t)(kc + kr) * ATTN + bc * 4);
            *(float4*)&Bs[kr][bc * 4] = bv;
        }
        __syncthreads();

#pragma unroll
        for (int k = 0; k < 32; k++) {
            const float4 av = *(const float4*)&As[k][tr * 4];
            unsigned long long a0 = dup2(av.x), a1 = dup2(av.y),
                               a2 = dup2(av.z), a3 = dup2(av.w);
            const ulonglong2 b01 = *(const ulonglong2*)&Bs[k][tc * 8];
            const ulonglong2 b23 = *(const ulonglong2*)&Bs[k][tc * 8 + 4];
            acc[0][0] = fma2(a0, b01.x, acc[0][0]);
            acc[0][1] = fma2(a0, b01.y, acc[0][1]);
            acc[0][2] = fma2(a0, b23.x, acc[0][2]);
            acc[0][3] = fma2(a0, b23.y, acc[0][3]);
            acc[1][0] = fma2(a1, b01.x, acc[1][0]);
            acc[1][1] = fma2(a1, b01.y, acc[1][1]);
            acc[1][2] = fma2(a1, b23.x, acc[1][2]);
            acc[1][3] = fma2(a1, b23.y, acc[1][3]);
            acc[2][0] = fma2(a2, b01.x, acc[2][0]);
            acc[2][1] = fma2(a2, b01.y, acc[2][1]);
            acc[2][2] = fma2(a2, b23.x, acc[2][2]);
            acc[2][3] = fma2(a2, b23.y, acc[2][3]);
            acc[3][0] = fma2(a3, b01.x, acc[3][0]);
            acc[3][1] = fma2(a3, b01.y, acc[3][1]);
            acc[3][2] = fma2(a3, b23.x, acc[3][2]);
            acc[3][3] = fma2(a3, b23.y, acc[3][3]);
        }
        __syncthreads();
    }

    // Epilogue: + hid, tanh, * v, partial sum over this thread's 8 cols
#pragma unroll
    for (int i = 0; i < 4; i++) {
        const int r = tr * 4 + i;
        const int b = r & 63;           // m0 is a multiple of 128
        const float* hb = g_hidb + b * ATTN;
        float p = 0.0f;
#pragma unroll
        for (int j = 0; j < 4; j++) {
            float x, y;
            unpack2(acc[i][j], x, y);
            const int c0 = tc * 8 + 2 * j;
            p += tanhf(x + hb[c0])     * v[c0];
            p += tanhf(y + hb[c0 + 1]) * v[c0 + 1];
        }
        red[tc][r] = p;
    }
    __syncthreads();
    if (tid < 128) {
        float s = 0.0f;
#pragma unroll
        for (int w = 0; w < 8; w++) s += red[w][tid];
        const int m = m0 + tid;
        g_scoresT[(m & 63) * L_SEQ + (m >> 6)] = s;  // transposed (b, l)
    }
}

// ---------------- Kernel 3a: per-b masked softmax stats ----------------
__global__ void __launch_bounds__(256) stats_kernel(const int* __restrict__ lens) {
    __shared__ float red[256];
    const int b = blockIdx.x;
    const int tid = threadIdx.x;
    const int len = lens[b];
    const float* s = g_scoresT + b * L_SEQ;

    float mx = -INFINITY;
    for (int l = tid; l < len; l += 256) mx = fmaxf(mx, s[l]);
    red[tid] = mx;
    __syncthreads();
    for (int o = 128; o > 0; o >>= 1) {
        if (tid < o) red[tid] = fmaxf(red[tid], red[tid + o]);
        __syncthreads();
    }
    mx = red[0];
    __syncthreads();

    float sum = 0.0f;
    for (int l = tid; l < len; l += 256) sum += expf(s[l] - mx);
    red[tid] = sum;
    __syncthreads();
    for (int o = 128; o > 0; o >>= 1) {
        if (tid < o) red[tid] += red[tid + o];
        __syncthreads();
    }
    if (tid == 0) {
        g_stats[b * 2 + 0] = mx;
        g_stats[b * 2 + 1] = 1.0f / red[0];
    }
}

// ---------------- Kernel 3b: weighted partial sums ----------------
__global__ void __launch_bounds__(256) weighted_kernel(const float* __restrict__ enc,
                                                       const int* __restrict__ lens) {
    __shared__ float wsh[128];
    const int s = blockIdx.x;
    const int b = blockIdx.y;
    const int tid = threadIdx.x;
    const int l0 = s * (L_SEQ / NSPLIT);
    const int len = lens[b];

    if (tid < 128) {
        const int l = l0 + tid;
        float w = 0.0f;
        if (l < len)
            w = expf(g_scoresT[b * L_SEQ + l] - g_stats[2 * b]) * g_stats[2 * b + 1];
        wsh[tid] = w;
    }
    __syncthreads();

    float a0 = 0.0f, a1 = 0.0f;
    if (l0 < len) {
        const int lim = min(128, len - l0);
        for (int i = 0; i < lim; i++) {
            const float w = wsh[i];
            const float* e = enc + ((size_t)(l0 + i) * B_BATCH + b) * ENC;
            a0 = fmaf(w, e[tid], a0);
            a1 = fmaf(w, e[tid + 256], a1);
        }
    }
    float* p = g_partial + ((size_t)(s * B_BATCH + b)) * ENC;
    p[tid] = a0;
    p[tid + 256] = a1;
}

// ---------------- Kernel 3c: reduce partials ----------------
__global__ void __launch_bounds__(256) reduce_kernel(float* __restrict__ out) {
    const int idx = blockIdx.x * 256 + threadIdx.x;  // 0..32767 == (b, d)
    float sum = 0.0f;
#pragma unroll
    for (int s = 0; s < NSPLIT; s++)
        sum += g_partial[(size_t)s * (B_BATCH * ENC) + idx];
    out[idx] = sum;
}

// ---------------- Launch ----------------
extern "C" void kernel_launch(void* const* d_in, const int* in_sizes, int n_in,
                              void* d_out, int out_size) {
    const float* enc    = (const float*)d_in[0];  // (L, B, 512)
    const int*   lens   = (const int*)d_in[1];    // (B,)
    const float* hidden = (const float*)d_in[2];  // (B, 512)
    const float* W_enc  = (const float*)d_in[3];  // (512, 64)
    const float* b_attn = (const float*)d_in[4];  // (64,)
    const float* W_hid  = (const float*)d_in[5];  // (512, 64)
    const float* v      = (const float*)d_in[6];  // (64,)
    float* out = (float*)d_out;                   // (B, 512)

    hid_kernel<<<B_BATCH, 64>>>(hidden, W_hid, b_attn);
    score_kernel<<<M_TOTAL / 128, 256>>>(enc, W_enc, v);
    stats_kernel<<<B_BATCH, 256>>>(lens);
    weighted_kernel<<<dim3(NSPLIT, B_BATCH), 256>>>(enc, lens);
    reduce_kernel<<<(B_BATCH * ENC) / 256, 256>>>(out);
}

// round 3
// speedup vs baseline: 1.3240x; 1.3240x over previous
#include <cuda_runtime.h>
#include <cuda_bf16.h>
#include <cstdint>
#include <math.h>

// Problem constants
#define L_SEQ 2048
#define B_BATCH 64
#define ENC 512
#define ATTN 64
#define HIDDEN 512
#define M_TOTAL (L_SEQ * B_BATCH)   // 131072
#define NSPLIT 16
#define NKSTEP 32                   // 512 / 16

// ---------------- device-global scratch (no allocs allowed) ----------------
__device__ float g_hidb[B_BATCH * ATTN];               // hid @ W_hidden + b_attn, (b, a)
__device__ float g_scoresT[B_BATCH * L_SEQ];           // scores transposed (b, l)
__device__ float g_stats[B_BATCH * 2];                 // per-b: max, 1/sumexp
__device__ float g_partial[NSPLIT * B_BATCH * ENC];    // partial weighted sums
// B fragments, mma-native: [kstep][ntile][lane] -> uint4(b0hi, b1hi, b0lo, b1lo)
__device__ uint4 g_Bfrag[NKSTEP * 8 * 32];

// ---------------- helpers ----------------
__device__ __forceinline__ unsigned pack_hi(float x, float y, unsigned& lo_out) {
    const __nv_bfloat16 hx = __float2bfloat16(x);
    const __nv_bfloat16 hy = __float2bfloat16(y);
    const __nv_bfloat16 lx = __float2bfloat16(x - __bfloat162float(hx));
    const __nv_bfloat16 ly = __float2bfloat16(y - __bfloat162float(hy));
    lo_out = ((unsigned)__bfloat16_as_ushort(ly) << 16) | __bfloat16_as_ushort(lx);
    return ((unsigned)__bfloat16_as_ushort(hy) << 16) | __bfloat16_as_ushort(hx);
}

__device__ __forceinline__ void mma_bf16(float* d, const unsigned* a, unsigned b0, unsigned b1) {
    asm volatile(
        "mma.sync.aligned.m16n8k16.row.col.f32.bf16.bf16.f32 "
        "{%0,%1,%2,%3}, {%4,%5,%6,%7}, {%8,%9}, {%0,%1,%2,%3};"
        : "+f"(d[0]), "+f"(d[1]), "+f"(d[2]), "+f"(d[3])
        : "r"(a[0]), "r"(a[1]), "r"(a[2]), "r"(a[3]), "r"(b0), "r"(b1));
}

// ---------------- Kernel 0: precompute B fragments (W_enc hi/lo, mma layout) ---------
__global__ void __launch_bounds__(256) prep_w_kernel(const float* __restrict__ W) {
    const int idx = blockIdx.x * 256 + threadIdx.x;   // 0 .. 8191
    if (idx >= NKSTEP * 8 * 32) return;
    const int lane = idx & 31;
    const int nt = (idx >> 5) & 7;
    const int s = idx >> 8;
    const int t = lane & 3;
    const int g = lane >> 2;
    const int n = nt * 8 + g;
    const int k0 = s * 16 + t * 2;
    uint4 r;
    unsigned lo;
    r.x = pack_hi(W[(size_t)k0 * ATTN + n],        W[(size_t)(k0 + 1) * ATTN + n], lo);
    r.z = lo;
    r.y = pack_hi(W[(size_t)(k0 + 8) * ATTN + n],  W[(size_t)(k0 + 9) * ATTN + n], lo);
    r.w = lo;
    g_Bfrag[idx] = r;
}

// ---------------- Kernel 1: hid = hidden @ W_hidden + b_attn ----------------
__global__ void __launch_bounds__(64) hid_kernel(const float* __restrict__ hidden,
                                                 const float* __restrict__ Wh,
                                                 const float* __restrict__ b_attn) {
    __shared__ float sh[HIDDEN];
    int b = blockIdx.x;
    int tid = threadIdx.x;
    for (int k = tid; k < HIDDEN; k += 64) sh[k] = hidden[b * HIDDEN + k];
    __syncthreads();
    float acc = b_attn[tid];
#pragma unroll 8
    for (int k = 0; k < HIDDEN; k++)
        acc = fmaf(sh[k], Wh[k * ATTN + tid], acc);
    g_hidb[b * ATTN + tid] = acc;
}

// ---------------- Kernel 2: bf16-split HMMA GEMM + tanh*v epilogue ----------------
// CTA: 256 threads = 8 warps; warp w owns rows [cta*128 + w*16, +16), all 64 cols.
// No smem, no syncs. A loaded fp32 from gmem (each element exactly once), split in regs.
__global__ void __launch_bounds__(256) score_kernel(const float* __restrict__ A,
                                                    const float* __restrict__ v) {
    const int tid = threadIdx.x;
    const int w = tid >> 5;
    const int lane = tid & 31;
    const int t = lane & 3;
    const int g = lane >> 2;
    const int m0w = blockIdx.x * 128 + w * 16;
    const int rowA = m0w + g;
    const int rowB = m0w + g + 8;
    const float* __restrict__ pA0 = A + (size_t)rowA * ENC + t * 2;
    const float* __restrict__ pA1 = A + (size_t)rowB * ENC + t * 2;

    float d[8][4];
#pragma unroll
    for (int nt = 0; nt < 8; nt++)
#pragma unroll
        for (int j = 0; j < 4; j++) d[nt][j] = 0.0f;

#pragma unroll 2
    for (int s = 0; s < NKSTEP; s++) {
        // B fragments for all 8 n-tiles (coalesced 128b loads, L1-resident)
        uint4 bf[8];
        const uint4* __restrict__ bp = g_Bfrag + (s << 8) + lane;
#pragma unroll
        for (int nt = 0; nt < 8; nt++) bf[nt] = bp[nt << 5];

        // A: 4x ld.64 fp32, split to bf16 hi/lo fragments
        const float2 x00 = *(const float2*)(pA0 + s * 16);
        const float2 x01 = *(const float2*)(pA0 + s * 16 + 8);
        const float2 x10 = *(const float2*)(pA1 + s * 16);
        const float2 x11 = *(const float2*)(pA1 + s * 16 + 8);
        unsigned ahi[4], alo[4];
        ahi[0] = pack_hi(x00.x, x00.y, alo[0]);
        ahi[1] = pack_hi(x10.x, x10.y, alo[1]);
        ahi[2] = pack_hi(x01.x, x01.y, alo[2]);
        ahi[3] = pack_hi(x11.x, x11.y, alo[3]);

#pragma unroll
        for (int nt = 0; nt < 8; nt++) {
            mma_bf16(d[nt], ahi, bf[nt].x, bf[nt].y);   // Ahi * Bhi
            mma_bf16(d[nt], ahi, bf[nt].z, bf[nt].w);   // Ahi * Blo
            mma_bf16(d[nt], alo, bf[nt].x, bf[nt].y);   // Alo * Bhi
        }
    }

    // Epilogue: scores = sum_n tanh(d + hid[b][n]) * v[n]
    const int b0 = rowA & 63;
    const int b1 = rowB & 63;
    const float* __restrict__ h0 = g_hidb + b0 * ATTN;
    const float* __restrict__ h1 = g_hidb + b1 * ATTN;
    float p0 = 0.0f, p1 = 0.0f;
#pragma unroll
    for (int nt = 0; nt < 8; nt++) {
        const int n0 = nt * 8 + t * 2;
        const float v0 = v[n0], v1 = v[n0 + 1];
        p0 += tanhf(d[nt][0] + h0[n0]) * v0 + tanhf(d[nt][1] + h0[n0 + 1]) * v1;
        p1 += tanhf(d[nt][2] + h1[n0]) * v0 + tanhf(d[nt][3] + h1[n0 + 1]) * v1;
    }
    // reduce across the 4 threads of each row-group
    p0 += __shfl_xor_sync(0xFFFFFFFFu, p0, 1);
    p0 += __shfl_xor_sync(0xFFFFFFFFu, p0, 2);
    p1 += __shfl_xor_sync(0xFFFFFFFFu, p1, 1);
    p1 += __shfl_xor_sync(0xFFFFFFFFu, p1, 2);
    if (t == 0) {
        g_scoresT[b0 * L_SEQ + (rowA >> 6)] = p0;
        g_scoresT[b1 * L_SEQ + (rowB >> 6)] = p1;
    }
}

// ---------------- Kernel 3a: per-b masked softmax stats ----------------
__global__ void __launch_bounds__(256) stats_kernel(const int* __restrict__ lens) {
    __shared__ float red[256];
    const int b = blockIdx.x;
    const int tid = threadIdx.x;
    const int len = lens[b];
    const float* s = g_scoresT + b * L_SEQ;

    float mx = -INFINITY;
    for (int l = tid; l < len; l += 256) mx = fmaxf(mx, s[l]);
    red[tid] = mx;
    __syncthreads();
    for (int o = 128; o > 0; o >>= 1) {
        if (tid < o) red[tid] = fmaxf(red[tid], red[tid + o]);
        __syncthreads();
    }
    mx = red[0];
    __syncthreads();

    float sum = 0.0f;
    for (int l = tid; l < len; l += 256) sum += expf(s[l] - mx);
    red[tid] = sum;
    __syncthreads();
    for (int o = 128; o > 0; o >>= 1) {
        if (tid < o) red[tid] += red[tid + o];
        __syncthreads();
    }
    if (tid == 0) {
        g_stats[b * 2 + 0] = mx;
        g_stats[b * 2 + 1] = 1.0f / red[0];
    }
}

// ---------------- Kernel 3b: weighted partial sums (float4, 2-way row split) ----------------
__global__ void __launch_bounds__(256) weighted_kernel(const float* __restrict__ enc,
                                                       const int* __restrict__ lens) {
    __shared__ float wsh[128];
    __shared__ float red[512];
    const int s = blockIdx.x;
    const int b = blockIdx.y;
    const int tid = threadIdx.x;
    const int l0 = s * (L_SEQ / NSPLIT);
    const int len = lens[b];
    float* pbase = g_partial + ((size_t)(s * B_BATCH + b)) * ENC;

    if (l0 >= len) {
        if (tid < 128) *(float4*)(pbase + tid * 4) = make_float4(0.f, 0.f, 0.f, 0.f);
        return;
    }

    if (tid < 128) {
        const int l = l0 + tid;
        float w = 0.0f;
        if (l < len)
            w = expf(g_scoresT[b * L_SEQ + l] - g_stats[2 * b]) * g_stats[2 * b + 1];
        wsh[tid] = w;
    }
    __syncthreads();

    const int lim = min(128, len - l0);
    const int d4 = tid & 127;
    const int half = tid >> 7;
    float4 acc = make_float4(0.f, 0.f, 0.f, 0.f);
#pragma unroll 4
    for (int i = half; i < lim; i += 2) {
        const float w = wsh[i];
        const float4 e = *(const float4*)(enc + ((size_t)(l0 + i) * B_BATCH + b) * ENC + d4 * 4);
        acc.x = fmaf(w, e.x, acc.x);
        acc.y = fmaf(w, e.y, acc.y);
        acc.z = fmaf(w, e.z, acc.z);
        acc.w = fmaf(w, e.w, acc.w);
    }
    if (half == 1) *(float4*)&red[d4 * 4] = acc;
    __syncthreads();
    if (half == 0) {
        const float4 o = *(const float4*)&red[d4 * 4];
        acc.x += o.x; acc.y += o.y; acc.z += o.z; acc.w += o.w;
        *(float4*)(pbase + d4 * 4) = acc;
    }
}

// ---------------- Kernel 3c: reduce partials ----------------
__global__ void __launch_bounds__(256) reduce_kernel(float* __restrict__ out) {
    const int idx = blockIdx.x * 256 + threadIdx.x;
    float4 sum = make_float4(0.f, 0.f, 0.f, 0.f);
#pragma unroll
    for (int s = 0; s < NSPLIT; s++) {
        const float4 p = *(const float4*)(g_partial + (size_t)s * (B_BATCH * ENC) + idx * 4);
        sum.x += p.x; sum.y += p.y; sum.z += p.z; sum.w += p.w;
    }
    *(float4*)(out + idx * 4) = sum;
}

// ---------------- Launch ----------------
extern "C" void kernel_launch(void* const* d_in, const int* in_sizes, int n_in,
                              void* d_out, int out_size) {
    const float* enc    = (const float*)d_in[0];  // (L, B, 512)
    const int*   lens   = (const int*)d_in[1];    // (B,)
    const float* hidden = (const float*)d_in[2];  // (B, 512)
    const float* W_enc  = (const float*)d_in[3];  // (512, 64)
    const float* b_attn = (const float*)d_in[4];  // (64,)
    const float* W_hid  = (const float*)d_in[5];  // (512, 64)
    const float* v      = (const float*)d_in[6];  // (64,)
    float* out = (float*)d_out;                   // (B, 512)

    prep_w_kernel<<<32, 256>>>(W_enc);
    hid_kernel<<<B_BATCH, 64>>>(hidden, W_hid, b_attn);
    score_kernel<<<M_TOTAL / 128, 256>>>(enc, v);
    stats_kernel<<<B_BATCH, 256>>>(lens);
    weighted_kernel<<<dim3(NSPLIT, B_BATCH), 256>>>(enc, lens);
    reduce_kernel<<<(B_BATCH * ENC) / (256 * 4), 256>>>(out);
}

// round 4
// speedup vs baseline: 1.7759x; 1.3413x over previous
#include <cuda_runtime.h>
#include <cuda_bf16.h>
#include <cuda_fp16.h>
#include <cstdint>
#include <math.h>

// Problem constants
#define L_SEQ 2048
#define B_BATCH 64
#define ENC 512
#define ATTN 64
#define HIDDEN 512
#define M_TOTAL (L_SEQ * B_BATCH)   // 131072
#define NSPLIT 16
#define NKSTEP 32                   // 512 / 16

// ---------------- device-global scratch (no allocs allowed) ----------------
__device__ float g_hidb[B_BATCH * ATTN];               // hid @ W_hidden + b_attn, (b, a)
__device__ float g_scoresT[B_BATCH * L_SEQ];           // scores transposed (b, l)
__device__ float g_stats[B_BATCH * 2];                 // per-b: max, 1/sumexp
__device__ float g_partial[NSPLIT * B_BATCH * ENC];    // partial weighted sums
// B fragments, mma-native: [kstep][ntile][lane] -> uint4(b0hi, b1hi, b0lo, b1lo), fp16x2
__device__ uint4 g_Bfrag[NKSTEP * 8 * 32];

// ---------------- helpers ----------------
__device__ __forceinline__ unsigned pack_h2(float x, float y) {
    const __half2 h = __float22half2_rn(make_float2(x, y));
    return *(const unsigned*)&h;
}
// fp16 hi/lo split for B (prep only)
__device__ __forceinline__ unsigned pack_hilo(float x, float y, unsigned& lo_out) {
    const __half hx = __float2half_rn(x);
    const __half hy = __float2half_rn(y);
    const __half lx = __float2half_rn(x - __half2float(hx));
    const __half ly = __float2half_rn(y - __half2float(hy));
    lo_out = ((unsigned)__half_as_ushort(ly) << 16) | __half_as_ushort(lx);
    return ((unsigned)__half_as_ushort(hy) << 16) | __half_as_ushort(hx);
}

__device__ __forceinline__ void mma_f16(float* d, const unsigned* a, unsigned b0, unsigned b1) {
    asm volatile(
        "mma.sync.aligned.m16n8k16.row.col.f32.f16.f16.f32 "
        "{%0,%1,%2,%3}, {%4,%5,%6,%7}, {%8,%9}, {%0,%1,%2,%3};"
        : "+f"(d[0]), "+f"(d[1]), "+f"(d[2]), "+f"(d[3])
        : "r"(a[0]), "r"(a[1]), "r"(a[2]), "r"(a[3]), "r"(b0), "r"(b1));
}

// ---------------- Kernel 0: precompute B fragments (W_enc fp16 hi/lo, mma layout) ----
__global__ void __launch_bounds__(256) prep_w_kernel(const float* __restrict__ W) {
    const int idx = blockIdx.x * 256 + threadIdx.x;   // 0 .. 8191
    if (idx >= NKSTEP * 8 * 32) return;
    const int lane = idx & 31;
    const int nt = (idx >> 5) & 7;
    const int s = idx >> 8;
    const int t = lane & 3;
    const int g = lane >> 2;
    const int n = nt * 8 + g;
    const int k0 = s * 16 + t * 2;
    uint4 r;
    unsigned lo;
    r.x = pack_hilo(W[(size_t)k0 * ATTN + n],       W[(size_t)(k0 + 1) * ATTN + n], lo);
    r.z = lo;
    r.y = pack_hilo(W[(size_t)(k0 + 8) * ATTN + n], W[(size_t)(k0 + 9) * ATTN + n], lo);
    r.w = lo;
    g_Bfrag[idx] = r;
}

// ---------------- Kernel 1: hid = hidden @ W_hidden + b_attn ----------------
__global__ void __launch_bounds__(64) hid_kernel(const float* __restrict__ hidden,
                                                 const float* __restrict__ Wh,
                                                 const float* __restrict__ b_attn) {
    __shared__ float sh[HIDDEN];
    int b = blockIdx.x;
    int tid = threadIdx.x;
    for (int k = tid; k < HIDDEN; k += 64) sh[k] = hidden[b * HIDDEN + k];
    __syncthreads();
    float acc = b_attn[tid];
#pragma unroll 8
    for (int k = 0; k < HIDDEN; k++)
        acc = fmaf(sh[k], Wh[k * ATTN + tid], acc);
    g_hidb[b * ATTN + tid] = acc;
}

// ---------------- Kernel 2: fp16 2-product HMMA GEMM + tanh*v epilogue ----------------
// CTA: 256 threads = 8 warps; warp w owns rows [cta*128 + w*16, +16), all 64 cols.
// A loaded fp32 (each element once), converted to fp16 hi only (lo dropped; B carries
// its own lo product so parts error ~2^-11/sqrt(3)).
__global__ void __launch_bounds__(256, 2) score_kernel(const float* __restrict__ A,
                                                       const float* __restrict__ v) {
    const int tid = threadIdx.x;
    const int w = tid >> 5;
    const int lane = tid & 31;
    const int t = lane & 3;
    const int g = lane >> 2;
    const int m0w = blockIdx.x * 128 + w * 16;
    const int rowA = m0w + g;
    const int rowB = m0w + g + 8;
    const float* __restrict__ pA0 = A + (size_t)rowA * ENC + t * 2;
    const float* __restrict__ pA1 = A + (size_t)rowB * ENC + t * 2;

    float d[8][4];
#pragma unroll
    for (int nt = 0; nt < 8; nt++)
#pragma unroll
        for (int j = 0; j < 4; j++) d[nt][j] = 0.0f;

#pragma unroll 2
    for (int s = 0; s < NKSTEP; s++) {
        // B fragments for all 8 n-tiles (coalesced 128b loads, L1-resident)
        uint4 bf[8];
        const uint4* __restrict__ bp = g_Bfrag + (s << 8) + lane;
#pragma unroll
        for (int nt = 0; nt < 8; nt++) bf[nt] = bp[nt << 5];

        // A: 4x ld.64 fp32 -> fp16x2 (hi only)
        const float2 x00 = *(const float2*)(pA0 + s * 16);
        const float2 x01 = *(const float2*)(pA0 + s * 16 + 8);
        const float2 x10 = *(const float2*)(pA1 + s * 16);
        const float2 x11 = *(const float2*)(pA1 + s * 16 + 8);
        unsigned ah[4];
        ah[0] = pack_h2(x00.x, x00.y);
        ah[1] = pack_h2(x10.x, x10.y);
        ah[2] = pack_h2(x01.x, x01.y);
        ah[3] = pack_h2(x11.x, x11.y);

#pragma unroll
        for (int nt = 0; nt < 8; nt++) {
            mma_f16(d[nt], ah, bf[nt].x, bf[nt].y);   // Ahi * Bhi
            mma_f16(d[nt], ah, bf[nt].z, bf[nt].w);   // Ahi * Blo
        }
    }

    // Epilogue: scores = sum_n tanh(d + hid[b][n]) * v[n]
    const int b0 = rowA & 63;
    const int b1 = rowB & 63;
    const float* __restrict__ h0 = g_hidb + b0 * ATTN;
    const float* __restrict__ h1 = g_hidb + b1 * ATTN;
    float p0 = 0.0f, p1 = 0.0f;
#pragma unroll
    for (int nt = 0; nt < 8; nt++) {
        const int n0 = nt * 8 + t * 2;
        const float v0 = v[n0], v1 = v[n0 + 1];
        p0 += tanhf(d[nt][0] + h0[n0]) * v0 + tanhf(d[nt][1] + h0[n0 + 1]) * v1;
        p1 += tanhf(d[nt][2] + h1[n0]) * v0 + tanhf(d[nt][3] + h1[n0 + 1]) * v1;
    }
    // reduce across the 4 threads of each row-group
    p0 += __shfl_xor_sync(0xFFFFFFFFu, p0, 1);
    p0 += __shfl_xor_sync(0xFFFFFFFFu, p0, 2);
    p1 += __shfl_xor_sync(0xFFFFFFFFu, p1, 1);
    p1 += __shfl_xor_sync(0xFFFFFFFFu, p1, 2);
    if (t == 0) {
        g_scoresT[b0 * L_SEQ + (rowA >> 6)] = p0;
        g_scoresT[b1 * L_SEQ + (rowB >> 6)] = p1;
    }
}

// ---------------- Kernel 3a: per-b masked softmax stats ----------------
__global__ void __launch_bounds__(256) stats_kernel(const int* __restrict__ lens) {
    __shared__ float red[256];
    const int b = blockIdx.x;
    const int tid = threadIdx.x;
    const int len = lens[b];
    const float* s = g_scoresT + b * L_SEQ;

    float mx = -INFINITY;
    for (int l = tid; l < len; l += 256) mx = fmaxf(mx, s[l]);
    red[tid] = mx;
    __syncthreads();
    for (int o = 128; o > 0; o >>= 1) {
        if (tid < o) red[tid] = fmaxf(red[tid], red[tid + o]);
        __syncthreads();
    }
    mx = red[0];
    __syncthreads();

    float sum = 0.0f;
    for (int l = tid; l < len; l += 256) sum += expf(s[l] - mx);
    red[tid] = sum;
    __syncthreads();
    for (int o = 128; o > 0; o >>= 1) {
        if (tid < o) red[tid] += red[tid + o];
        __syncthreads();
    }
    if (tid == 0) {
        g_stats[b * 2 + 0] = mx;
        g_stats[b * 2 + 1] = 1.0f / red[0];
    }
}

// ---------------- Kernel 3b: weighted partial sums (float4, 2-way row split) ----------------
__global__ void __launch_bounds__(256) weighted_kernel(const float* __restrict__ enc,
                                                       const int* __restrict__ lens) {
    __shared__ float wsh[128];
    __shared__ float red[512];
    const int s = blockIdx.x;
    const int b = blockIdx.y;
    const int tid = threadIdx.x;
    const int l0 = s * (L_SEQ / NSPLIT);
    const int len = lens[b];
    float* pbase = g_partial + ((size_t)(s * B_BATCH + b)) * ENC;

    if (l0 >= len) {
        if (tid < 128) *(float4*)(pbase + tid * 4) = make_float4(0.f, 0.f, 0.f, 0.f);
        return;
    }

    if (tid < 128) {
        const int l = l0 + tid;
        float w = 0.0f;
        if (l < len)
            w = expf(g_scoresT[b * L_SEQ + l] - g_stats[2 * b]) * g_stats[2 * b + 1];
        wsh[tid] = w;
    }
    __syncthreads();

    const int lim = min(128, len - l0);
    const int d4 = tid & 127;
    const int half = tid >> 7;
    float4 acc = make_float4(0.f, 0.f, 0.f, 0.f);
#pragma unroll 4
    for (int i = half; i < lim; i += 2) {
        const float w = wsh[i];
        const float4 e = *(const float4*)(enc + ((size_t)(l0 + i) * B_BATCH + b) * ENC + d4 * 4);
        acc.x = fmaf(w, e.x, acc.x);
        acc.y = fmaf(w, e.y, acc.y);
        acc.z = fmaf(w, e.z, acc.z);
        acc.w = fmaf(w, e.w, acc.w);
    }
    if (half == 1) *(float4*)&red[d4 * 4] = acc;
    __syncthreads();
    if (half == 0) {
        const float4 o = *(const float4*)&red[d4 * 4];
        acc.x += o.x; acc.y += o.y; acc.z += o.z; acc.w += o.w;
        *(float4*)(pbase + d4 * 4) = acc;
    }
}

// ---------------- Kernel 3c: reduce partials ----------------
__global__ void __launch_bounds__(256) reduce_kernel(float* __restrict__ out) {
    const int idx = blockIdx.x * 256 + threadIdx.x;
    float4 sum = make_float4(0.f, 0.f, 0.f, 0.f);
#pragma unroll
    for (int s = 0; s < NSPLIT; s++) {
        const float4 p = *(const float4*)(g_partial + (size_t)s * (B_BATCH * ENC) + idx * 4);
        sum.x += p.x; sum.y += p.y; sum.z += p.z; sum.w += p.w;
    }
    *(float4*)(out + idx * 4) = sum;
}

// ---------------- Launch ----------------
extern "C" void kernel_launch(void* const* d_in, const int* in_sizes, int n_in,
                              void* d_out, int out_size) {
    const float* enc    = (const float*)d_in[0];  // (L, B, 512)
    const int*   lens   = (const int*)d_in[1];    // (B,)
    const float* hidden = (const float*)d_in[2];  // (B, 512)
    const float* W_enc  = (const float*)d_in[3];  // (512, 64)
    const float* b_attn = (const float*)d_in[4];  // (64,)
    const float* W_hid  = (const float*)d_in[5];  // (512, 64)
    const float* v      = (const float*)d_in[6];  // (64,)
    float* out = (float*)d_out;                   // (B, 512)

    prep_w_kernel<<<32, 256>>>(W_enc);
    hid_kernel<<<B_BATCH, 64>>>(hidden, W_hid, b_attn);
    score_kernel<<<M_TOTAL / 128, 256>>>(enc, v);
    stats_kernel<<<B_BATCH, 256>>>(lens);
    weighted_kernel<<<dim3(NSPLIT, B_BATCH), 256>>>(enc, lens);
    reduce_kernel<<<(B_BATCH * ENC) / (256 * 4), 256>>>(out);
}

// round 5
// speedup vs baseline: 1.8673x; 1.0515x over previous
#include <cuda_runtime.h>
#include <cuda_bf16.h>
#include <cuda_fp16.h>
#include <cstdint>
#include <math.h>

// Problem constants
#define L_SEQ 2048
#define B_BATCH 64
#define ENC 512
#define ATTN 64
#define HIDDEN 512
#define M_TOTAL (L_SEQ * B_BATCH)   // 131072
#define NSPLIT 16
#define NKSTEP 32                   // 512 / 16

// ---------------- device-global scratch (no allocs allowed) ----------------
__device__ float g_hidb[B_BATCH * ATTN];               // hid @ W_hidden + b_attn, (b, a)
__device__ float g_scoresT[B_BATCH * L_SEQ];           // scores transposed (b, l)
__device__ float g_stats[B_BATCH * 2];                 // per-b: max, 1/sumexp
__device__ float g_partial[NSPLIT * B_BATCH * ENC];    // partial weighted sums
// B fragments, mma-native: [kstep][ntile][lane] -> uint4(b0hi, b1hi, b0lo, b1lo), fp16x2
__device__ uint4 g_Bfrag[NKSTEP * 8 * 32];

// ---------------- helpers ----------------
__device__ __forceinline__ unsigned pack_h2(float x, float y) {
    const __half2 h = __float22half2_rn(make_float2(x, y));
    return *(const unsigned*)&h;
}
// fp16 hi/lo split for B (prep only)
__device__ __forceinline__ unsigned pack_hilo(float x, float y, unsigned& lo_out) {
    const __half hx = __float2half_rn(x);
    const __half hy = __float2half_rn(y);
    const __half lx = __float2half_rn(x - __half2float(hx));
    const __half ly = __float2half_rn(y - __half2float(hy));
    lo_out = ((unsigned)__half_as_ushort(ly) << 16) | __half_as_ushort(lx);
    return ((unsigned)__half_as_ushort(hy) << 16) | __half_as_ushort(hx);
}

__device__ __forceinline__ void mma_f16(float* d, const unsigned* a, unsigned b0, unsigned b1) {
    asm volatile(
        "mma.sync.aligned.m16n8k16.row.col.f32.f16.f16.f32 "
        "{%0,%1,%2,%3}, {%4,%5,%6,%7}, {%8,%9}, {%0,%1,%2,%3};"
        : "+f"(d[0]), "+f"(d[1]), "+f"(d[2]), "+f"(d[3])
        : "r"(a[0]), "r"(a[1]), "r"(a[2]), "r"(a[3]), "r"(b0), "r"(b1));
}

// ---------------- Kernel 0: precompute B fragments (W_enc fp16 hi/lo, mma layout) ----
__global__ void __launch_bounds__(256) prep_w_kernel(const float* __restrict__ W) {
    const int idx = blockIdx.x * 256 + threadIdx.x;   // 0 .. 8191
    if (idx >= NKSTEP * 8 * 32) return;
    const int lane = idx & 31;
    const int nt = (idx >> 5) & 7;
    const int s = idx >> 8;
    const int t = lane & 3;
    const int g = lane >> 2;
    const int n = nt * 8 + g;
    const int k0 = s * 16 + t * 2;
    uint4 r;
    unsigned lo;
    r.x = pack_hilo(W[(size_t)k0 * ATTN + n],       W[(size_t)(k0 + 1) * ATTN + n], lo);
    r.z = lo;
    r.y = pack_hilo(W[(size_t)(k0 + 8) * ATTN + n], W[(size_t)(k0 + 9) * ATTN + n], lo);
    r.w = lo;
    g_Bfrag[idx] = r;
}

// ---------------- Kernel 1: hid = hidden @ W_hidden + b_attn ----------------
__global__ void __launch_bounds__(64) hid_kernel(const float* __restrict__ hidden,
                                                 const float* __restrict__ Wh,
                                                 const float* __restrict__ b_attn) {
    __shared__ float sh[HIDDEN];
    int b = blockIdx.x;
    int tid = threadIdx.x;
    for (int k = tid; k < HIDDEN; k += 64) sh[k] = hidden[b * HIDDEN + k];
    __syncthreads();
    float acc = b_attn[tid];
#pragma unroll 8
    for (int k = 0; k < HIDDEN; k++)
        acc = fmaf(sh[k], Wh[k * ATTN + tid], acc);
    g_hidb[b * ATTN + tid] = acc;
}

// ---------------- Kernel 2: fp16 2-product HMMA GEMM + tanh*v epilogue ----------------
// CTA: 256 threads = 8 warps; warp w owns rows [cta*256 + w*32, +32) as TWO m16 tiles
// sharing each B fragment load (halves L1tex crossbar traffic per M-row).
__global__ void __launch_bounds__(256, 2) score_kernel(const float* __restrict__ A,
                                                       const float* __restrict__ v) {
    const int tid = threadIdx.x;
    const int w = tid >> 5;
    const int lane = tid & 31;
    const int t = lane & 3;
    const int g = lane >> 2;
    const int m0w = blockIdx.x * 256 + w * 32;
    const int r0 = m0w + g;          // mtile0 rows: r0, r0+8
    const int r2 = m0w + g + 16;     // mtile1 rows: r2, r2+8
    const float* __restrict__ pA0 = A + (size_t)r0 * ENC + t * 2;
    const float* __restrict__ pA1 = A + (size_t)(r0 + 8) * ENC + t * 2;
    const float* __restrict__ pA2 = A + (size_t)r2 * ENC + t * 2;
    const float* __restrict__ pA3 = A + (size_t)(r2 + 8) * ENC + t * 2;

    float d0[8][4], d1[8][4];
#pragma unroll
    for (int nt = 0; nt < 8; nt++)
#pragma unroll
        for (int j = 0; j < 4; j++) { d0[nt][j] = 0.0f; d1[nt][j] = 0.0f; }

    for (int s = 0; s < NKSTEP; s++) {
        // A: 8x ld.64 fp32 -> fp16x2 (hi only)
        const float2 x00 = *(const float2*)(pA0 + s * 16);
        const float2 x01 = *(const float2*)(pA0 + s * 16 + 8);
        const float2 x10 = *(const float2*)(pA1 + s * 16);
        const float2 x11 = *(const float2*)(pA1 + s * 16 + 8);
        const float2 x20 = *(const float2*)(pA2 + s * 16);
        const float2 x21 = *(const float2*)(pA2 + s * 16 + 8);
        const float2 x30 = *(const float2*)(pA3 + s * 16);
        const float2 x31 = *(const float2*)(pA3 + s * 16 + 8);
        unsigned a0[4], a1[4];
        a0[0] = pack_h2(x00.x, x00.y);
        a0[1] = pack_h2(x10.x, x10.y);
        a0[2] = pack_h2(x01.x, x01.y);
        a0[3] = pack_h2(x11.x, x11.y);
        a1[0] = pack_h2(x20.x, x20.y);
        a1[1] = pack_h2(x30.x, x30.y);
        a1[2] = pack_h2(x21.x, x21.y);
        a1[3] = pack_h2(x31.x, x31.y);

        const uint4* __restrict__ bp = g_Bfrag + (s << 8) + lane;
#pragma unroll
        for (int nt = 0; nt < 8; nt++) {
            const uint4 bf = bp[nt << 5];
            mma_f16(d0[nt], a0, bf.x, bf.y);   // Ahi * Bhi
            mma_f16(d0[nt], a0, bf.z, bf.w);   // Ahi * Blo
            mma_f16(d1[nt], a1, bf.x, bf.y);
            mma_f16(d1[nt], a1, bf.z, bf.w);
        }
    }

    // Epilogue: scores = sum_n tanh(d + hid[b][n]) * v[n]; 4 rows per lane-group
    const int rows[4] = { r0, r0 + 8, r2, r2 + 8 };
    float p[4] = { 0.f, 0.f, 0.f, 0.f };
#pragma unroll
    for (int nt = 0; nt < 8; nt++) {
        const int n0 = nt * 8 + t * 2;
        const float v0 = v[n0], v1 = v[n0 + 1];
#pragma unroll
        for (int rr = 0; rr < 4; rr++) {
            const float* hb = g_hidb + (rows[rr] & 63) * ATTN;
            const float e0 = (rr < 2) ? d0[nt][(rr & 1) * 2]     : d1[nt][(rr & 1) * 2];
            const float e1 = (rr < 2) ? d0[nt][(rr & 1) * 2 + 1] : d1[nt][(rr & 1) * 2 + 1];
            p[rr] += tanhf(e0 + hb[n0]) * v0 + tanhf(e1 + hb[n0 + 1]) * v1;
        }
    }
#pragma unroll
    for (int rr = 0; rr < 4; rr++) {
        p[rr] += __shfl_xor_sync(0xFFFFFFFFu, p[rr], 1);
        p[rr] += __shfl_xor_sync(0xFFFFFFFFu, p[rr], 2);
    }
    if (t == 0) {
#pragma unroll
        for (int rr = 0; rr < 4; rr++)
            g_scoresT[(rows[rr] & 63) * L_SEQ + (rows[rr] >> 6)] = p[rr];
    }
}

// ---------------- Kernel 3a: per-b masked softmax stats (smem-staged) ----------------
__global__ void __launch_bounds__(256) stats_kernel(const int* __restrict__ lens) {
    __shared__ float red[32];
    const int b = blockIdx.x;
    const int tid = threadIdx.x;
    const int lane = tid & 31;
    const int wrp = tid >> 5;
    const int len = lens[b];
    const float* s = g_scoresT + b * L_SEQ;

    float vals[8];
#pragma unroll
    for (int i = 0; i < 2; i++) {
        const float4 f = *(const float4*)(s + (i * 256 + tid) * 4);
        vals[i * 4 + 0] = f.x; vals[i * 4 + 1] = f.y;
        vals[i * 4 + 2] = f.z; vals[i * 4 + 3] = f.w;
    }
    float mx = -INFINITY;
#pragma unroll
    for (int i = 0; i < 2; i++)
#pragma unroll
        for (int j = 0; j < 4; j++) {
            const int l = (i * 256 + tid) * 4 + j;
            if (l < len) mx = fmaxf(mx, vals[i * 4 + j]);
        }
#pragma unroll
    for (int o = 16; o > 0; o >>= 1) mx = fmaxf(mx, __shfl_xor_sync(0xFFFFFFFFu, mx, o));
    if (lane == 0) red[wrp] = mx;
    __syncthreads();
    if (wrp == 0) {
        float m = (lane < 8) ? red[lane] : -INFINITY;
#pragma unroll
        for (int o = 4; o > 0; o >>= 1) m = fmaxf(m, __shfl_xor_sync(0xFFFFFFFFu, m, o));
        if (lane == 0) red[16] = m;
    }
    __syncthreads();
    mx = red[16];

    float sum = 0.0f;
#pragma unroll
    for (int i = 0; i < 2; i++)
#pragma unroll
        for (int j = 0; j < 4; j++) {
            const int l = (i * 256 + tid) * 4 + j;
            if (l < len) sum += expf(vals[i * 4 + j] - mx);
        }
#pragma unroll
    for (int o = 16; o > 0; o >>= 1) sum += __shfl_xor_sync(0xFFFFFFFFu, sum, o);
    if (lane == 0) red[wrp] = sum;
    __syncthreads();
    if (tid == 0) {
        float tot = 0.0f;
#pragma unroll
        for (int i = 0; i < 8; i++) tot += red[i];
        g_stats[b * 2 + 0] = mx;
        g_stats[b * 2 + 1] = 1.0f / tot;
    }
}

// ---------------- Kernel 3b: weighted partial sums (float4, 2-way row split) ----------------
__global__ void __launch_bounds__(256) weighted_kernel(const float* __restrict__ enc,
                                                       const int* __restrict__ lens) {
    __shared__ float wsh[128];
    __shared__ float red[512];
    const int s = blockIdx.x;
    const int b = blockIdx.y;
    const int tid = threadIdx.x;
    const int l0 = s * (L_SEQ / NSPLIT);
    const int len = lens[b];
    float* pbase = g_partial + ((size_t)(s * B_BATCH + b)) * ENC;

    if (l0 >= len) {
        if (tid < 128) *(float4*)(pbase + tid * 4) = make_float4(0.f, 0.f, 0.f, 0.f);
        return;
    }

    if (tid < 128) {
        const int l = l0 + tid;
        float w = 0.0f;
        if (l < len)
            w = expf(g_scoresT[b * L_SEQ + l] - g_stats[2 * b]) * g_stats[2 * b + 1];
        wsh[tid] = w;
    }
    __syncthreads();

    const int lim = min(128, len - l0);
    const int d4 = tid & 127;
    const int half = tid >> 7;
    float4 acc = make_float4(0.f, 0.f, 0.f, 0.f);
#pragma unroll 4
    for (int i = half; i < lim; i += 2) {
        const float w = wsh[i];
        const float4 e = *(const float4*)(enc + ((size_t)(l0 + i) * B_BATCH + b) * ENC + d4 * 4);
        acc.x = fmaf(w, e.x, acc.x);
        acc.y = fmaf(w, e.y, acc.y);
        acc.z = fmaf(w, e.z, acc.z);
        acc.w = fmaf(w, e.w, acc.w);
    }
    if (half == 1) *(float4*)&red[d4 * 4] = acc;
    __syncthreads();
    if (half == 0) {
        const float4 o = *(const float4*)&red[d4 * 4];
        acc.x += o.x; acc.y += o.y; acc.z += o.z; acc.w += o.w;
        *(float4*)(pbase + d4 * 4) = acc;
    }
}

// ---------------- Kernel 3c: reduce partials ----------------
__global__ void __launch_bounds__(256) reduce_kernel(float* __restrict__ out) {
    const int idx = blockIdx.x * 256 + threadIdx.x;
    float4 sum = make_float4(0.f, 0.f, 0.f, 0.f);
#pragma unroll
    for (int s = 0; s < NSPLIT; s++) {
        const float4 p = *(const float4*)(g_partial + (size_t)s * (B_BATCH * ENC) + idx * 4);
        sum.x += p.x; sum.y += p.y; sum.z += p.z; sum.w += p.w;
    }
    *(float4*)(out + idx * 4) = sum;
}

// ---------------- Launch ----------------
extern "C" void kernel_launch(void* const* d_in, const int* in_sizes, int n_in,
                              void* d_out, int out_size) {
    const float* enc    = (const float*)d_in[0];  // (L, B, 512)
    const int*   lens   = (const int*)d_in[1];    // (B,)
    const float* hidden = (const float*)d_in[2];  // (B, 512)
    const float* W_enc  = (const float*)d_in[3];  // (512, 64)
    const float* b_attn = (const float*)d_in[4];  // (64,)
    const float* W_hid  = (const float*)d_in[5];  // (512, 64)
    const float* v      = (const float*)d_in[6];  // (64,)
    float* out = (float*)d_out;                   // (B, 512)

    prep_w_kernel<<<32, 256>>>(W_enc);
    hid_kernel<<<B_BATCH, 64>>>(hidden, W_hid, b_attn);
    score_kernel<<<M_TOTAL / 256, 256>>>(enc, v);
    stats_kernel<<<B_BATCH, 256>>>(lens);
    weighted_kernel<<<dim3(NSPLIT, B_BATCH), 256>>>(enc, lens);
    reduce_kernel<<<(B_BATCH * ENC) / (256 * 4), 256>>>(out);
}